// round 4
// baseline (speedup 1.0000x reference)
#include <cuda_runtime.h>
#include <cstdint>

// Problem constants
#define BB 64
#define HH 1024
#define II 512
#define MIN_TAU 1e-3f
#define LOG2E 1.4426950408889634f

// Tiling: block = 8 o-rows (one per warp), loops over BITERS batches.
#define OW 8
#define BITERS 8
#define OGROUPS (HH / OW)       // 128
#define BGROUPS (BB / BITERS)   // 8
#define STAGES 3

// Per-warp private ring: 3 stages x 4KB (one gumbel row each).
#define ROW_BYTES (HH * 4)                       // 4096
#define WARP_RING_BYTES (STAGES * ROW_BYTES)     // 12288
#define DATA_BYTES (OW * WARP_RING_BYTES)        // 98304
#define MBAR_OFF DATA_BYTES
#define SMEM_BYTES (MBAR_OFF + OW * STAGES * 8)  // + 24 mbarriers

static __device__ __forceinline__ uint32_t s2u(const void* p) {
    uint32_t a;
    asm("{ .reg .u64 t; cvta.to.shared.u64 t, %1; cvt.u32.u64 %0, t; }"
        : "=r"(a) : "l"(p));
    return a;
}

static __device__ __forceinline__ void mbar_init(uint32_t mbar, uint32_t cnt) {
    asm volatile("mbarrier.init.shared.b64 [%0], %1;" :: "r"(mbar), "r"(cnt) : "memory");
}

static __device__ __forceinline__ void mbar_expect_tx(uint32_t mbar, uint32_t bytes) {
    asm volatile("mbarrier.arrive.expect_tx.shared.b64 _, [%0], %1;"
                 :: "r"(mbar), "r"(bytes) : "memory");
}

static __device__ __forceinline__ void mbar_wait(uint32_t mbar, uint32_t parity) {
    uint32_t done;
    asm volatile(
        "{\n\t.reg .pred p;\n\t"
        "mbarrier.try_wait.parity.acquire.cta.shared::cta.b64 p, [%1], %2;\n\t"
        "selp.b32 %0, 1, 0, p;\n\t}"
        : "=r"(done) : "r"(mbar), "r"(parity) : "memory");
    if (!done) {
        asm volatile(
            "{\n\t.reg .pred P1;\n\t"
            "WL_%=:\n\t"
            "mbarrier.try_wait.parity.acquire.cta.shared::cta.b64 P1, [%0], %1, 0x989680;\n\t"
            "@P1 bra.uni WD_%=;\n\t"
            "bra.uni WL_%=;\n\t"
            "WD_%=:\n\t}"
            :: "r"(mbar), "r"(parity) : "memory");
    }
}

static __device__ __forceinline__ void bulk_copy(uint32_t dst_smem, const void* src,
                                                 uint32_t bytes, uint32_t mbar) {
    asm volatile(
        "cp.async.bulk.shared::cta.global.mbarrier::complete_tx::bytes [%0], [%1], %2, [%3];"
        :: "r"(dst_smem), "l"(src), "r"(bytes), "r"(mbar) : "memory");
}

static __device__ __forceinline__ void fence_async_smem() {
    asm volatile("fence.proxy.async.shared::cta;" ::: "memory");
}

static __device__ __forceinline__ float ex2(float x) {
    float y;
    asm("ex2.approx.ftz.f32 %0, %1;" : "=f"(y) : "f"(x));
    return y;
}

// Fused ReservoirRNNCell step — warp-autonomous TMA pipeline.
// Each warp owns o-row (og*8 + w) and streams gumbel[b, o, :] rows through a
// PRIVATE 3-stage x 4KB smem ring via cp.async.bulk, waiting only on its own
// mbarrier. No __syncthreads in the main loop: refill happens the moment this
// warp is done reading its buffer (fence.proxy.async covers the generic-read
// -> async-write hazard). W_hh row lives pre-scaled (1/tau * log2e) in 32
// regs; W_ih row in 16 regs; h_prev/x_t are L2/L1-resident LDGs.
// Softmax without max-subtraction is safe: logits bounded (~18.5 from Gumbel
// with u in [1e-8,1-1e-8]); validated rel_err 3.4e-7 in R1-R3.
__global__ __launch_bounds__(256, 2) void reservoir_cell_kernel(
    const float* __restrict__ x_t,         // (B, I)
    const float* __restrict__ h_prev,      // (B, H)
    const float* __restrict__ W_ih,        // (H, I)
    const float* __restrict__ b_ih,        // (H,)
    const float* __restrict__ W_hh,        // (H, H)
    const float* __restrict__ temperature, // scalar
    const float* __restrict__ gumbel,      // (B, H, H)
    float* __restrict__ out)               // (B, H)
{
    extern __shared__ float smem[];
    const uint32_t smem_u = s2u(smem);

    const int og = blockIdx.x % OGROUPS;
    const int bg = blockIdx.x / OGROUPS;
    const int b0 = bg * BITERS;

    const int tid  = threadIdx.x;
    const int w    = tid >> 5;
    const int lane = tid & 31;
    const int o    = og * OW + w;

    const uint32_t ring_u  = smem_u + (uint32_t)w * WARP_RING_BYTES;
    const uint32_t mbar_w  = smem_u + MBAR_OFF + (uint32_t)w * (STAGES * 8);
    const float*   ring_f  = smem + (size_t)w * (WARP_RING_BYTES / 4);

    // ---- init this warp's mbarriers, sync once, then prologue fills ----
    if (lane == 0) {
#pragma unroll
        for (int j = 0; j < STAGES; ++j) mbar_init(mbar_w + 8u * j, 1);
    }
    __syncthreads();  // all mbarriers initialized before any TMA completes

    const float* grow0 = gumbel + ((size_t)b0 * HH + o) * HH;
    if (lane == 0) {
#pragma unroll
        for (int j = 0; j < STAGES; ++j) {
            const uint32_t mb = mbar_w + 8u * j;
            mbar_expect_tx(mb, ROW_BYTES);
            bulk_copy(ring_u + j * ROW_BYTES, grow0 + (size_t)j * HH * HH, ROW_BYTES, mb);
        }
    }

    // ---- per-warp register constants (overlap with prologue TMA) ----
    const float inv_tau_l2e = LOG2E / fmaxf(temperature[0], MIN_TAU);
    const float bias = b_ih[o];

    const float4* __restrict__ whr = reinterpret_cast<const float4*>(W_hh + (size_t)o * HH);
    float4 wp[8];
#pragma unroll
    for (int k = 0; k < 8; ++k) {
        float4 v = whr[lane + 32 * k];
        v.x *= inv_tau_l2e; v.y *= inv_tau_l2e;
        v.z *= inv_tau_l2e; v.w *= inv_tau_l2e;
        wp[k] = v;
    }
    const float4* __restrict__ wir = reinterpret_cast<const float4*>(W_ih + (size_t)o * II);
    float4 wih[4];
#pragma unroll
    for (int k = 0; k < 4; ++k) wih[k] = wir[lane + 32 * k];

    // ---- main loop: warp-private 3-deep pipeline over BITERS batches ----
    int st = 0, parity = 0;
    for (int i = 0; i < BITERS; ++i) {
        const int b = b0 + i;

        // input contribution (L1/L2-resident) — overlaps the pipeline wait
        const float4* __restrict__ xr = reinterpret_cast<const float4*>(x_t + (size_t)b * II);
        float ic = 0.0f;
#pragma unroll
        for (int k = 0; k < 4; ++k) {
            const float4 xv = xr[lane + 32 * k];
            ic = fmaf(xv.x, wih[k].x, ic);
            ic = fmaf(xv.y, wih[k].y, ic);
            ic = fmaf(xv.z, wih[k].z, ic);
            ic = fmaf(xv.w, wih[k].w, ic);
        }

        mbar_wait(mbar_w + 8u * st, parity);

        const float4* __restrict__ gs =
            reinterpret_cast<const float4*>(ring_f + (size_t)st * HH);
        const float4* __restrict__ hr =
            reinterpret_cast<const float4*>(h_prev + (size_t)b * HH);

        float s = 0.0f, t = 0.0f;
#pragma unroll
        for (int k = 0; k < 8; ++k) {
            const int idx = lane + 32 * k;
            const float4 g = gs[idx];
            const float4 h = hr[idx];   // L2/L1 hit: row reused by 128 blocks
            float e;
            e = ex2(fmaf(g.x, LOG2E, wp[k].x)); s += e; t = fmaf(e, h.x, t);
            e = ex2(fmaf(g.y, LOG2E, wp[k].y)); s += e; t = fmaf(e, h.y, t);
            e = ex2(fmaf(g.z, LOG2E, wp[k].z)); s += e; t = fmaf(e, h.z, t);
            e = ex2(fmaf(g.w, LOG2E, wp[k].w)); s += e; t = fmaf(e, h.w, t);
        }

        // buffer free for this warp -> refill immediately (no block sync)
        __syncwarp();
        if (lane == 0 && i + STAGES < BITERS) {
            fence_async_smem();  // order our generic reads before async write
            const uint32_t mb = mbar_w + 8u * st;
            mbar_expect_tx(mb, ROW_BYTES);
            bulk_copy(ring_u + st * ROW_BYTES,
                      gumbel + ((size_t)(b0 + i + STAGES) * HH + o) * HH,
                      ROW_BYTES, mb);
        }

        // warp reductions + output
#pragma unroll
        for (int off = 16; off > 0; off >>= 1) {
            s  += __shfl_xor_sync(0xffffffffu, s,  off);
            t  += __shfl_xor_sync(0xffffffffu, t,  off);
            ic += __shfl_xor_sync(0xffffffffu, ic, off);
        }
        if (lane == 0) {
            out[(size_t)b * HH + o] = tanhf(ic + bias + t / s);
        }

        if (++st == STAGES) { st = 0; parity ^= 1; }
    }
}

extern "C" void kernel_launch(void* const* d_in, const int* in_sizes, int n_in,
                              void* d_out, int out_size) {
    // metadata order: x_t, h_prev, W_ih, b_ih, W_hh, temperature, gumbel_noise
    const float* x_t    = (const float*)d_in[0];
    const float* h_prev = (const float*)d_in[1];
    const float* W_ih   = (const float*)d_in[2];
    const float* b_ih   = (const float*)d_in[3];
    const float* W_hh   = (const float*)d_in[4];
    const float* temp   = (const float*)d_in[5];
    const float* gum    = (const float*)d_in[6];
    float* out = (float*)d_out;

    static bool attr_set = false;
    if (!attr_set) {
        cudaFuncSetAttribute(reservoir_cell_kernel,
                             cudaFuncAttributeMaxDynamicSharedMemorySize, SMEM_BYTES);
        attr_set = true;
    }

    dim3 grid(OGROUPS * BGROUPS);  // 128 * 8 = 1024 blocks
    dim3 block(OW * 32);           // 256 threads, 8 warps
    reservoir_cell_kernel<<<grid, block, SMEM_BYTES>>>(
        x_t, h_prev, W_ih, b_ih, W_hh, temp, gum, out);
}

// round 5
// speedup vs baseline: 1.0310x; 1.0310x over previous
#include <cuda_runtime.h>
#include <cstdint>

// Problem constants
#define BB 64
#define HH 1024
#define II 512
#define MIN_TAU 1e-3f
#define LOG2E 1.4426950408889634f

// Tiling
#define OW 8                       // o-rows per block (one per warp)
#define BITERS 8                   // b iterations per block
#define OGROUPS (HH / OW)          // 128
#define BGROUPS (BB / BITERS)      // 8
#define STAGES 2

// SMEM layout (dynamic)
#define G_BYTES (OW * HH * 4)            // 32768: gumbel[b, og*8 .. og*8+7, :]
#define H_BYTES (HH * 4)                 // 4096:  h_prev[b, :]
#define STAGE_BYTES (G_BYTES + H_BYTES)  // 36864
#define MBAR_OFF (STAGES * STAGE_BYTES)  // 73728
#define SMEM_BYTES (MBAR_OFF + 2 * 8)    // 73744 -> 3 CTAs/SM fit (221KB < 228KB)

static __device__ __forceinline__ uint32_t s2u(const void* p) {
    uint32_t a;
    asm("{ .reg .u64 t; cvta.to.shared.u64 t, %1; cvt.u32.u64 %0, t; }"
        : "=r"(a) : "l"(p));
    return a;
}

static __device__ __forceinline__ void mbar_init(uint32_t mbar, uint32_t cnt) {
    asm volatile("mbarrier.init.shared.b64 [%0], %1;" :: "r"(mbar), "r"(cnt) : "memory");
}

static __device__ __forceinline__ void mbar_expect_tx(uint32_t mbar, uint32_t bytes) {
    asm volatile("mbarrier.arrive.expect_tx.shared.b64 _, [%0], %1;"
                 :: "r"(mbar), "r"(bytes) : "memory");
}

static __device__ __forceinline__ void mbar_wait(uint32_t mbar, uint32_t parity) {
    uint32_t done;
    asm volatile(
        "{\n\t.reg .pred p;\n\t"
        "mbarrier.try_wait.parity.acquire.cta.shared::cta.b64 p, [%1], %2;\n\t"
        "selp.b32 %0, 1, 0, p;\n\t}"
        : "=r"(done) : "r"(mbar), "r"(parity) : "memory");
    if (!done) {
        asm volatile(
            "{\n\t.reg .pred P1;\n\t"
            "WL_%=:\n\t"
            "mbarrier.try_wait.parity.acquire.cta.shared::cta.b64 P1, [%0], %1, 0x989680;\n\t"
            "@P1 bra.uni WD_%=;\n\t"
            "bra.uni WL_%=;\n\t"
            "WD_%=:\n\t}"
            :: "r"(mbar), "r"(parity) : "memory");
    }
}

static __device__ __forceinline__ void bulk_copy(uint32_t dst_smem, const void* src,
                                                 uint32_t bytes, uint32_t mbar) {
    asm volatile(
        "cp.async.bulk.shared::cta.global.mbarrier::complete_tx::bytes [%0], [%1], %2, [%3];"
        :: "r"(dst_smem), "l"(src), "r"(bytes), "r"(mbar) : "memory");
}

static __device__ __forceinline__ float ex2(float x) {
    float y;
    asm("ex2.approx.ftz.f32 %0, %1;" : "=f"(y) : "f"(x));
    return y;
}

// Fused ReservoirRNNCell step, block-level TMA smem pipeline (R3 structure)
// tuned for 3 CTAs/SM:
//   block = 8 contiguous o-rows (8 warps) x 8 b-iterations; per iteration ONE
//   32KB cp.async.bulk for gumbel[b, o0:o0+8, :] + 4KB for h_prev[b,:] into a
//   2-stage smem ring. __launch_bounds__(256,3) caps regs (~85) so occupancy
//   is smem-limited at 3 CTAs (221KB/SM): 3 independent fill streams per SM,
//   24 warps. W_ih row caching in regs was dropped (L1-resident, reloaded per
//   iteration) to make the register budget.
// Softmax without max-subtraction is safe: logits bounded (~18.5); validated
// rel_err 3.4e-7 across R1-R4.
__global__ __launch_bounds__(256, 3) void reservoir_cell_kernel(
    const float* __restrict__ x_t,         // (B, I)
    const float* __restrict__ h_prev,      // (B, H)
    const float* __restrict__ W_ih,        // (H, I)
    const float* __restrict__ b_ih,        // (H,)
    const float* __restrict__ W_hh,        // (H, H)
    const float* __restrict__ temperature, // scalar
    const float* __restrict__ gumbel,      // (B, H, H)
    float* __restrict__ out)               // (B, H)
{
    extern __shared__ float smem[];
    const uint32_t smem_u = s2u(smem);
    const uint32_t mbar0 = smem_u + MBAR_OFF;

    const int og = blockIdx.x % OGROUPS;
    const int bg = blockIdx.x / OGROUPS;
    const int b0 = bg * BITERS;
    const int o0 = og * OW;

    const int tid  = threadIdx.x;
    const int w    = tid >> 5;
    const int lane = tid & 31;
    const int o    = o0 + w;

    // ---- init barriers + prologue fills (stages 0 and 1) ----
    if (tid == 0) {
        mbar_init(mbar0, 1);
        mbar_init(mbar0 + 8, 1);
    }
    __syncthreads();
    if (tid == 0) {
#pragma unroll
        for (int j = 0; j < STAGES; ++j) {
            const uint32_t mb = mbar0 + 8u * j;
            mbar_expect_tx(mb, STAGE_BYTES);
            const float* gsrc = gumbel + ((size_t)(b0 + j) * HH + o0) * HH;
            bulk_copy(smem_u + j * STAGE_BYTES, gsrc, G_BYTES, mb);
            const float* hsrc = h_prev + (size_t)(b0 + j) * HH;
            bulk_copy(smem_u + j * STAGE_BYTES + G_BYTES, hsrc, H_BYTES, mb);
        }
    }

    // ---- per-warp constants: pre-scaled W_hh row in 32 regs ----
    const float inv_tau_l2e = LOG2E / fmaxf(temperature[0], MIN_TAU);
    const float bias = b_ih[o];

    const float4* __restrict__ whr = reinterpret_cast<const float4*>(W_hh + (size_t)o * HH);
    float4 wp[8];
#pragma unroll
    for (int k = 0; k < 8; ++k) {
        float4 v = whr[lane + 32 * k];
        v.x *= inv_tau_l2e; v.y *= inv_tau_l2e;
        v.z *= inv_tau_l2e; v.w *= inv_tau_l2e;
        wp[k] = v;
    }
    const float4* __restrict__ wir = reinterpret_cast<const float4*>(W_ih + (size_t)o * II);

    // ---- main loop over 8 b's with 2-stage pipeline ----
    for (int i = 0; i < BITERS; ++i) {
        const int st = i & 1;
        const uint32_t parity = (i >> 1) & 1;
        const int b = b0 + i;

        // input contribution: W_ih row is L1-resident (reused 8x per warp),
        // x_t row L1/L2-resident. Overlaps the TMA wait.
        const float4* __restrict__ xr = reinterpret_cast<const float4*>(x_t + (size_t)b * II);
        float ic = 0.0f;
#pragma unroll
        for (int k = 0; k < 4; ++k) {
            const float4 xv = xr[lane + 32 * k];
            const float4 wv = wir[lane + 32 * k];
            ic = fmaf(xv.x, wv.x, ic);
            ic = fmaf(xv.y, wv.y, ic);
            ic = fmaf(xv.z, wv.z, ic);
            ic = fmaf(xv.w, wv.w, ic);
        }

        mbar_wait(mbar0 + 8u * st, parity);

        const float4* __restrict__ gs = reinterpret_cast<const float4*>(
            smem + (size_t)st * (STAGE_BYTES / 4) + (size_t)w * HH);
        const float4* __restrict__ hs = reinterpret_cast<const float4*>(
            smem + (size_t)st * (STAGE_BYTES / 4) + G_BYTES / 4);

        float s = 0.0f, t = 0.0f;
#pragma unroll
        for (int k = 0; k < 8; ++k) {
            const int idx = lane + 32 * k;
            const float4 g = gs[idx];
            const float4 h = hs[idx];
            float e;
            e = ex2(fmaf(g.x, LOG2E, wp[k].x)); s += e; t = fmaf(e, h.x, t);
            e = ex2(fmaf(g.y, LOG2E, wp[k].y)); s += e; t = fmaf(e, h.y, t);
            e = ex2(fmaf(g.z, LOG2E, wp[k].z)); s += e; t = fmaf(e, h.z, t);
            e = ex2(fmaf(g.w, LOG2E, wp[k].w)); s += e; t = fmaf(e, h.w, t);
        }

        // stage consumed by all warps -> refill ASAP, then do the epilogue
        // math (reductions/tanh) UNDER the fresh fill.
        __syncthreads();
        if (tid == 0 && i + STAGES < BITERS) {
            const int j = i + STAGES;
            const uint32_t mb = mbar0 + 8u * st;
            mbar_expect_tx(mb, STAGE_BYTES);
            const float* gsrc = gumbel + ((size_t)j * HH + o0) * HH + (size_t)b0 * HH * HH;
            bulk_copy(smem_u + st * STAGE_BYTES, gsrc, G_BYTES, mb);
            const float* hsrc = h_prev + (size_t)(b0 + j) * HH;
            bulk_copy(smem_u + st * STAGE_BYTES + G_BYTES, hsrc, H_BYTES, mb);
        }

        // warp reductions + output (overlaps the refill)
#pragma unroll
        for (int off = 16; off > 0; off >>= 1) {
            s  += __shfl_xor_sync(0xffffffffu, s,  off);
            t  += __shfl_xor_sync(0xffffffffu, t,  off);
            ic += __shfl_xor_sync(0xffffffffu, ic, off);
        }
        if (lane == 0) {
            out[(size_t)b * HH + o] = tanhf(ic + bias + t / s);
        }
    }
}

extern "C" void kernel_launch(void* const* d_in, const int* in_sizes, int n_in,
                              void* d_out, int out_size) {
    // metadata order: x_t, h_prev, W_ih, b_ih, W_hh, temperature, gumbel_noise
    const float* x_t    = (const float*)d_in[0];
    const float* h_prev = (const float*)d_in[1];
    const float* W_ih   = (const float*)d_in[2];
    const float* b_ih   = (const float*)d_in[3];
    const float* W_hh   = (const float*)d_in[4];
    const float* temp   = (const float*)d_in[5];
    const float* gum    = (const float*)d_in[6];
    float* out = (float*)d_out;

    static bool attr_set = false;
    if (!attr_set) {
        cudaFuncSetAttribute(reservoir_cell_kernel,
                             cudaFuncAttributeMaxDynamicSharedMemorySize, SMEM_BYTES);
        attr_set = true;
    }

    dim3 grid(OGROUPS * BGROUPS);  // 128 * 8 = 1024 blocks
    dim3 block(OW * 32);           // 256 threads, 8 warps
    reservoir_cell_kernel<<<grid, block, SMEM_BYTES>>>(
        x_t, h_prev, W_ih, b_ih, W_hh, temp, gum, out);
}

// round 6
// speedup vs baseline: 1.0745x; 1.0422x over previous
#include <cuda_runtime.h>
#include <cstdint>

// Problem constants
#define BB 64
#define HH 1024
#define II 512
#define MIN_TAU 1e-3f
#define LOG2E 1.4426950408889634f

// Tiling
#define OW 8                       // o-rows per block (one per warp)
#define BITERS 4                   // b iterations per block (fine granularity)
#define OGROUPS (HH / OW)          // 128
#define BGROUPS (BB / BITERS)      // 16
#define STAGES 3

// SMEM layout (dynamic)
#define G_BYTES (OW * HH * 4)            // 32768: gumbel[b, o0 .. o0+7, :]
#define H_BYTES (HH * 4)                 // 4096:  h_prev[b, :]
#define STAGE_BYTES (G_BYTES + H_BYTES)  // 36864
#define MBAR_OFF (STAGES * STAGE_BYTES)  // 110592
#define SMEM_BYTES (MBAR_OFF + STAGES * 8)  // 110616 -> 2 CTAs/SM (221KB<=228KB)

static __device__ __forceinline__ uint32_t s2u(const void* p) {
    uint32_t a;
    asm("{ .reg .u64 t; cvta.to.shared.u64 t, %1; cvt.u32.u64 %0, t; }"
        : "=r"(a) : "l"(p));
    return a;
}

static __device__ __forceinline__ void mbar_init(uint32_t mbar, uint32_t cnt) {
    asm volatile("mbarrier.init.shared.b64 [%0], %1;" :: "r"(mbar), "r"(cnt) : "memory");
}

static __device__ __forceinline__ void mbar_expect_tx(uint32_t mbar, uint32_t bytes) {
    asm volatile("mbarrier.arrive.expect_tx.shared.b64 _, [%0], %1;"
                 :: "r"(mbar), "r"(bytes) : "memory");
}

static __device__ __forceinline__ void mbar_wait(uint32_t mbar, uint32_t parity) {
    uint32_t done;
    asm volatile(
        "{\n\t.reg .pred p;\n\t"
        "mbarrier.try_wait.parity.acquire.cta.shared::cta.b64 p, [%1], %2;\n\t"
        "selp.b32 %0, 1, 0, p;\n\t}"
        : "=r"(done) : "r"(mbar), "r"(parity) : "memory");
    if (!done) {
        asm volatile(
            "{\n\t.reg .pred P1;\n\t"
            "WL_%=:\n\t"
            "mbarrier.try_wait.parity.acquire.cta.shared::cta.b64 P1, [%0], %1, 0x989680;\n\t"
            "@P1 bra.uni WD_%=;\n\t"
            "bra.uni WL_%=;\n\t"
            "WD_%=:\n\t}"
            :: "r"(mbar), "r"(parity) : "memory");
    }
}

static __device__ __forceinline__ void bulk_copy(uint32_t dst_smem, const void* src,
                                                 uint32_t bytes, uint32_t mbar) {
    asm volatile(
        "cp.async.bulk.shared::cta.global.mbarrier::complete_tx::bytes [%0], [%1], %2, [%3];"
        :: "r"(dst_smem), "l"(src), "r"(bytes), "r"(mbar) : "memory");
}

static __device__ __forceinline__ float ex2(float x) {
    float y;
    asm("ex2.approx.ftz.f32 %0, %1;" : "=f"(y) : "f"(x));
    return y;
}

// Fused ReservoirRNNCell step — block-level TMA smem pipeline, 3-deep.
//   block = 8 contiguous o-rows (8 warps) x 4 b-iterations.
//   Per b ONE 32KB cp.async.bulk (gumbel[b, o0:o0+8, :]) + 4KB (h_prev[b,:])
//   into a 3-stage smem ring -> up to 2 pending fills per CTA, ~144KB/SM
//   in-flight at 2 CTAs/SM (vs 72KB with 2 stages): covers loaded DRAM
//   latency per Little's law. BITERS=4 -> grid 2048 -> 6.9 waves: wave-
//   quantization loss drops from ~15% (3.46 waves) to ~1%.
//   W_hh row pre-scaled (1/tau * log2e) in 32 regs; W_ih row in 16 regs
//   (2 CTAs/SM leaves regs for both). __syncthreads fires only on refill
//   iterations (uniform condition), i.e. once per CTA.
// Softmax without max-subtraction is safe: logits bounded (~18.5);
// validated rel_err 3.4e-7 across R1-R5.
__global__ __launch_bounds__(256, 2) void reservoir_cell_kernel(
    const float* __restrict__ x_t,         // (B, I)
    const float* __restrict__ h_prev,      // (B, H)
    const float* __restrict__ W_ih,        // (H, I)
    const float* __restrict__ b_ih,        // (H,)
    const float* __restrict__ W_hh,        // (H, H)
    const float* __restrict__ temperature, // scalar
    const float* __restrict__ gumbel,      // (B, H, H)
    float* __restrict__ out)               // (B, H)
{
    extern __shared__ float smem[];
    const uint32_t smem_u = s2u(smem);
    const uint32_t mbar0 = smem_u + MBAR_OFF;

    const int og = blockIdx.x % OGROUPS;
    const int bg = blockIdx.x / OGROUPS;
    const int b0 = bg * BITERS;
    const int o0 = og * OW;

    const int tid  = threadIdx.x;
    const int w    = tid >> 5;
    const int lane = tid & 31;
    const int o    = o0 + w;

    // ---- init barriers + prologue fills (stages 0..2) ----
    if (tid == 0) {
#pragma unroll
        for (int j = 0; j < STAGES; ++j) mbar_init(mbar0 + 8u * j, 1);
    }
    __syncthreads();
    if (tid == 0) {
#pragma unroll
        for (int j = 0; j < STAGES; ++j) {
            const uint32_t mb = mbar0 + 8u * j;
            mbar_expect_tx(mb, STAGE_BYTES);
            const float* gsrc = gumbel + ((size_t)(b0 + j) * HH + o0) * HH;
            bulk_copy(smem_u + j * STAGE_BYTES, gsrc, G_BYTES, mb);
            const float* hsrc = h_prev + (size_t)(b0 + j) * HH;
            bulk_copy(smem_u + j * STAGE_BYTES + G_BYTES, hsrc, H_BYTES, mb);
        }
    }

    // ---- per-warp constants (overlap the prologue TMA) ----
    const float inv_tau_l2e = LOG2E / fmaxf(temperature[0], MIN_TAU);
    const float bias = b_ih[o];

    const float4* __restrict__ whr = reinterpret_cast<const float4*>(W_hh + (size_t)o * HH);
    float4 wp[8];
#pragma unroll
    for (int k = 0; k < 8; ++k) {
        float4 v = whr[lane + 32 * k];
        v.x *= inv_tau_l2e; v.y *= inv_tau_l2e;
        v.z *= inv_tau_l2e; v.w *= inv_tau_l2e;
        wp[k] = v;
    }
    const float4* __restrict__ wir = reinterpret_cast<const float4*>(W_ih + (size_t)o * II);
    float4 wih[4];
#pragma unroll
    for (int k = 0; k < 4; ++k) wih[k] = wir[lane + 32 * k];

    // ---- main loop over 4 b's through the 3-stage ring ----
#pragma unroll
    for (int i = 0; i < BITERS; ++i) {
        const int st = i % STAGES;
        const uint32_t parity = (i / STAGES) & 1;
        const int b = b0 + i;

        // input contribution (register-cached W_ih) — overlaps the wait
        const float4* __restrict__ xr = reinterpret_cast<const float4*>(x_t + (size_t)b * II);
        float ic = 0.0f;
#pragma unroll
        for (int k = 0; k < 4; ++k) {
            const float4 xv = xr[lane + 32 * k];
            ic = fmaf(xv.x, wih[k].x, ic);
            ic = fmaf(xv.y, wih[k].y, ic);
            ic = fmaf(xv.z, wih[k].z, ic);
            ic = fmaf(xv.w, wih[k].w, ic);
        }

        mbar_wait(mbar0 + 8u * st, parity);

        const float4* __restrict__ gs = reinterpret_cast<const float4*>(
            smem + (size_t)st * (STAGE_BYTES / 4) + (size_t)w * HH);
        const float4* __restrict__ hs = reinterpret_cast<const float4*>(
            smem + (size_t)st * (STAGE_BYTES / 4) + G_BYTES / 4);

        float s = 0.0f, t = 0.0f;
#pragma unroll
        for (int k = 0; k < 8; ++k) {
            const int idx = lane + 32 * k;
            const float4 g = gs[idx];
            const float4 h = hs[idx];
            float e;
            e = ex2(fmaf(g.x, LOG2E, wp[k].x)); s += e; t = fmaf(e, h.x, t);
            e = ex2(fmaf(g.y, LOG2E, wp[k].y)); s += e; t = fmaf(e, h.y, t);
            e = ex2(fmaf(g.z, LOG2E, wp[k].z)); s += e; t = fmaf(e, h.z, t);
            e = ex2(fmaf(g.w, LOG2E, wp[k].w)); s += e; t = fmaf(e, h.w, t);
        }

        // refill only needed while i + STAGES < BITERS (i == 0 here);
        // condition is uniform across the block so the sync is legal.
        if (i + STAGES < BITERS) {
            __syncthreads();
            if (tid == 0) {
                const int j = i + STAGES;
                const uint32_t mb = mbar0 + 8u * st;
                mbar_expect_tx(mb, STAGE_BYTES);
                const float* gsrc = gumbel + ((size_t)(b0 + j) * HH + o0) * HH;
                bulk_copy(smem_u + st * STAGE_BYTES, gsrc, G_BYTES, mb);
                const float* hsrc = h_prev + (size_t)(b0 + j) * HH;
                bulk_copy(smem_u + st * STAGE_BYTES + G_BYTES, hsrc, H_BYTES, mb);
            }
        }

        // warp reductions + output (overlaps any refill)
#pragma unroll
        for (int off = 16; off > 0; off >>= 1) {
            s  += __shfl_xor_sync(0xffffffffu, s,  off);
            t  += __shfl_xor_sync(0xffffffffu, t,  off);
            ic += __shfl_xor_sync(0xffffffffu, ic, off);
        }
        if (lane == 0) {
            out[(size_t)b * HH + o] = tanhf(ic + bias + t / s);
        }
    }
}

extern "C" void kernel_launch(void* const* d_in, const int* in_sizes, int n_in,
                              void* d_out, int out_size) {
    // metadata order: x_t, h_prev, W_ih, b_ih, W_hh, temperature, gumbel_noise
    const float* x_t    = (const float*)d_in[0];
    const float* h_prev = (const float*)d_in[1];
    const float* W_ih   = (const float*)d_in[2];
    const float* b_ih   = (const float*)d_in[3];
    const float* W_hh   = (const float*)d_in[4];
    const float* temp   = (const float*)d_in[5];
    const float* gum    = (const float*)d_in[6];
    float* out = (float*)d_out;

    static bool attr_set = false;
    if (!attr_set) {
        cudaFuncSetAttribute(reservoir_cell_kernel,
                             cudaFuncAttributeMaxDynamicSharedMemorySize, SMEM_BYTES);
        attr_set = true;
    }

    dim3 grid(OGROUPS * BGROUPS);  // 128 * 16 = 2048 blocks
    dim3 block(OW * 32);           // 256 threads, 8 warps
    reservoir_cell_kernel<<<grid, block, SMEM_BYTES>>>(
        x_t, h_prev, W_ih, b_ih, W_hh, temp, gum, out);
}

// round 7
// speedup vs baseline: 1.1596x; 1.0792x over previous
#include <cuda_runtime.h>
#include <cstdint>

// Problem constants
#define BB 64
#define HH 1024
#define II 512
#define MIN_TAU 1e-3f
#define LOG2E 1.4426950408889634f

// Tiling: 256 resident CTAs (single wave on 148 SMs x 2 CTAs).
// CTA = fixed o-group of 8 rows x 32 b-iterations.
#define OW 8
#define BITERS 32
#define OGROUPS (HH / OW)       // 128
#define HALVES (BB / BITERS)    // 2
#define STAGES 3

// SMEM layout (dynamic)
#define G_BYTES (OW * HH * 4)            // 32768: gumbel[b, o0 .. o0+7, :]
#define H_BYTES (HH * 4)                 // 4096:  h_prev[b, :]
#define STAGE_BYTES (G_BYTES + H_BYTES)  // 36864
#define MBAR_OFF (STAGES * STAGE_BYTES)  // 110592
#define SMEM_BYTES (MBAR_OFF + STAGES * 8)  // 110616 -> 2 CTAs/SM (221KB <= 228KB)

static __device__ __forceinline__ uint32_t s2u(const void* p) {
    uint32_t a;
    asm("{ .reg .u64 t; cvta.to.shared.u64 t, %1; cvt.u32.u64 %0, t; }"
        : "=r"(a) : "l"(p));
    return a;
}

static __device__ __forceinline__ void mbar_init(uint32_t mbar, uint32_t cnt) {
    asm volatile("mbarrier.init.shared.b64 [%0], %1;" :: "r"(mbar), "r"(cnt) : "memory");
}

static __device__ __forceinline__ void mbar_expect_tx(uint32_t mbar, uint32_t bytes) {
    asm volatile("mbarrier.arrive.expect_tx.shared.b64 _, [%0], %1;"
                 :: "r"(mbar), "r"(bytes) : "memory");
}

static __device__ __forceinline__ void mbar_wait(uint32_t mbar, uint32_t parity) {
    uint32_t done;
    asm volatile(
        "{\n\t.reg .pred p;\n\t"
        "mbarrier.try_wait.parity.acquire.cta.shared::cta.b64 p, [%1], %2;\n\t"
        "selp.b32 %0, 1, 0, p;\n\t}"
        : "=r"(done) : "r"(mbar), "r"(parity) : "memory");
    if (!done) {
        asm volatile(
            "{\n\t.reg .pred P1;\n\t"
            "WL_%=:\n\t"
            "mbarrier.try_wait.parity.acquire.cta.shared::cta.b64 P1, [%0], %1, 0x989680;\n\t"
            "@P1 bra.uni WD_%=;\n\t"
            "bra.uni WL_%=;\n\t"
            "WD_%=:\n\t}"
            :: "r"(mbar), "r"(parity) : "memory");
    }
}

static __device__ __forceinline__ void bulk_copy(uint32_t dst_smem, const void* src,
                                                 uint32_t bytes, uint32_t mbar) {
    asm volatile(
        "cp.async.bulk.shared::cta.global.mbarrier::complete_tx::bytes [%0], [%1], %2, [%3];"
        :: "r"(dst_smem), "l"(src), "r"(bytes), "r"(mbar) : "memory");
}

static __device__ __forceinline__ void fence_async_smem() {
    asm volatile("fence.proxy.async.shared::cta;" ::: "memory");
}

static __device__ __forceinline__ float ex2(float x) {
    float y;
    asm("ex2.approx.ftz.f32 %0, %1;" : "=f"(y) : "f"(x));
    return y;
}

// Fused ReservoirRNNCell step — single-wave resident TMA pipeline.
//   grid = 256 CTAs (one wave at 2 CTAs/SM): zero wave transitions.
//   CTA = o-group og (8 rows; W_hh pre-scaled into 32 regs ONCE) x 32
//   b-iterations through a 3-stage smem ring (32KB gumbel + 4KB h_prev per
//   stage). Per-iteration refill after __syncthreads keeps 2-3 fills in
//   flight per CTA for ~29/32 iterations: true steady state, prologue
//   amortized 32x. fence.proxy.async before each refill orders the CTA's
//   generic-proxy smem reads before the async-proxy TMA rewrite (R6's
//   rel_err wobble is suspected to be this missing fence).
// Softmax without max-subtraction is safe: logits bounded (~18.5 from
// Gumbel with u in [1e-8, 1-1e-8]); validated rel_err 3.4e-7 in R1-R5.
__global__ __launch_bounds__(256, 2) void reservoir_cell_kernel(
    const float* __restrict__ x_t,         // (B, I)
    const float* __restrict__ h_prev,      // (B, H)
    const float* __restrict__ W_ih,        // (H, I)
    const float* __restrict__ b_ih,        // (H,)
    const float* __restrict__ W_hh,        // (H, H)
    const float* __restrict__ temperature, // scalar
    const float* __restrict__ gumbel,      // (B, H, H)
    float* __restrict__ out)               // (B, H)
{
    extern __shared__ float smem[];
    const uint32_t smem_u = s2u(smem);
    const uint32_t mbar0 = smem_u + MBAR_OFF;

    const int og   = blockIdx.x & (OGROUPS - 1);   // 0..127
    const int half = blockIdx.x >> 7;              // 0..1
    const int b0 = half * BITERS;
    const int o0 = og * OW;

    const int tid  = threadIdx.x;
    const int w    = tid >> 5;
    const int lane = tid & 31;
    const int o    = o0 + w;

    // ---- init barriers + prologue fills (stages 0..2) ----
    if (tid == 0) {
#pragma unroll
        for (int j = 0; j < STAGES; ++j) mbar_init(mbar0 + 8u * j, 1);
    }
    __syncthreads();
    if (tid == 0) {
#pragma unroll
        for (int j = 0; j < STAGES; ++j) {
            const uint32_t mb = mbar0 + 8u * j;
            mbar_expect_tx(mb, STAGE_BYTES);
            const float* gsrc = gumbel + ((size_t)(b0 + j) * HH + o0) * HH;
            bulk_copy(smem_u + j * STAGE_BYTES, gsrc, G_BYTES, mb);
            const float* hsrc = h_prev + (size_t)(b0 + j) * HH;
            bulk_copy(smem_u + j * STAGE_BYTES + G_BYTES, hsrc, H_BYTES, mb);
        }
    }

    // ---- per-warp constants, loaded ONCE per 32 tiles (overlaps TMA) ----
    const float inv_tau_l2e = LOG2E / fmaxf(temperature[0], MIN_TAU);
    const float bias = b_ih[o];

    const float4* __restrict__ whr = reinterpret_cast<const float4*>(W_hh + (size_t)o * HH);
    float4 wp[8];
#pragma unroll
    for (int k = 0; k < 8; ++k) {
        float4 v = whr[lane + 32 * k];
        v.x *= inv_tau_l2e; v.y *= inv_tau_l2e;
        v.z *= inv_tau_l2e; v.w *= inv_tau_l2e;
        wp[k] = v;
    }
    const float4* __restrict__ wir = reinterpret_cast<const float4*>(W_ih + (size_t)o * II);
    float4 wih[4];
#pragma unroll
    for (int k = 0; k < 4; ++k) wih[k] = wir[lane + 32 * k];

    // ---- steady-state loop over 32 b's through the 3-stage ring ----
    int st = 0;
    int parity = 0;
    for (int i = 0; i < BITERS; ++i) {
        const int b = b0 + i;

        // input contribution (register-cached W_ih) — overlaps the wait
        const float4* __restrict__ xr = reinterpret_cast<const float4*>(x_t + (size_t)b * II);
        float ic = 0.0f;
#pragma unroll
        for (int k = 0; k < 4; ++k) {
            const float4 xv = xr[lane + 32 * k];
            ic = fmaf(xv.x, wih[k].x, ic);
            ic = fmaf(xv.y, wih[k].y, ic);
            ic = fmaf(xv.z, wih[k].z, ic);
            ic = fmaf(xv.w, wih[k].w, ic);
        }

        mbar_wait(mbar0 + 8u * st, parity);

        const float4* __restrict__ gs = reinterpret_cast<const float4*>(
            smem + (size_t)st * (STAGE_BYTES / 4) + (size_t)w * HH);
        const float4* __restrict__ hs = reinterpret_cast<const float4*>(
            smem + (size_t)st * (STAGE_BYTES / 4) + G_BYTES / 4);

        float s = 0.0f, t = 0.0f;
#pragma unroll
        for (int k = 0; k < 8; ++k) {
            const int idx = lane + 32 * k;
            const float4 g = gs[idx];
            const float4 h = hs[idx];
            float e;
            e = ex2(fmaf(g.x, LOG2E, wp[k].x)); s += e; t = fmaf(e, h.x, t);
            e = ex2(fmaf(g.y, LOG2E, wp[k].y)); s += e; t = fmaf(e, h.y, t);
            e = ex2(fmaf(g.z, LOG2E, wp[k].z)); s += e; t = fmaf(e, h.z, t);
            e = ex2(fmaf(g.w, LOG2E, wp[k].w)); s += e; t = fmaf(e, h.w, t);
        }

        // stage consumed by all warps -> refill for tile i+3, then do the
        // epilogue math under the fresh fill.
        __syncthreads();
        if (tid == 0 && i + STAGES < BITERS) {
            fence_async_smem();  // generic reads of this stage before async rewrite
            const int j = b0 + i + STAGES;
            const uint32_t mb = mbar0 + 8u * st;
            mbar_expect_tx(mb, STAGE_BYTES);
            const float* gsrc = gumbel + ((size_t)j * HH + o0) * HH;
            bulk_copy(smem_u + st * STAGE_BYTES, gsrc, G_BYTES, mb);
            const float* hsrc = h_prev + (size_t)j * HH;
            bulk_copy(smem_u + st * STAGE_BYTES + G_BYTES, hsrc, H_BYTES, mb);
        }

        // warp reductions + output (overlaps the refill)
#pragma unroll
        for (int off = 16; off > 0; off >>= 1) {
            s  += __shfl_xor_sync(0xffffffffu, s,  off);
            t  += __shfl_xor_sync(0xffffffffu, t,  off);
            ic += __shfl_xor_sync(0xffffffffu, ic, off);
        }
        if (lane == 0) {
            out[(size_t)b * HH + o] = tanhf(ic + bias + t / s);
        }

        if (++st == STAGES) { st = 0; parity ^= 1; }
    }
}

extern "C" void kernel_launch(void* const* d_in, const int* in_sizes, int n_in,
                              void* d_out, int out_size) {
    // metadata order: x_t, h_prev, W_ih, b_ih, W_hh, temperature, gumbel_noise
    const float* x_t    = (const float*)d_in[0];
    const float* h_prev = (const float*)d_in[1];
    const float* W_ih   = (const float*)d_in[2];
    const float* b_ih   = (const float*)d_in[3];
    const float* W_hh   = (const float*)d_in[4];
    const float* temp   = (const float*)d_in[5];
    const float* gum    = (const float*)d_in[6];
    float* out = (float*)d_out;

    static bool attr_set = false;
    if (!attr_set) {
        cudaFuncSetAttribute(reservoir_cell_kernel,
                             cudaFuncAttributeMaxDynamicSharedMemorySize, SMEM_BYTES);
        attr_set = true;
    }

    dim3 grid(OGROUPS * HALVES);   // 128 * 2 = 256 CTAs: one resident wave
    dim3 block(OW * 32);           // 256 threads, 8 warps
    reservoir_cell_kernel<<<grid, block, SMEM_BYTES>>>(
        x_t, h_prev, W_ih, b_ih, W_hh, temp, gum, out);
}

// round 8
// speedup vs baseline: 1.1992x; 1.0342x over previous
#include <cuda_runtime.h>
#include <cstdint>

// Problem constants
#define BB 64
#define HH 1024
#define II 512
#define MIN_TAU 1e-3f
#define LOG2E 1.4426950408889634f

// Tiling: 256 resident CTAs (single wave on 148 SMs x 2 CTAs).
// CTA = fixed o-group of 8 rows x 32 b-iterations.
#define OW 8
#define BITERS 32
#define OGROUPS (HH / OW)       // 128
#define HALVES (BB / BITERS)    // 2
#define STAGES 3

// SMEM layout (dynamic)
#define G_BYTES (OW * HH * 4)            // 32768: gumbel[b, o0 .. o0+7, :]
#define H_BYTES (HH * 4)                 // 4096:  h_prev[b, :]
#define STAGE_BYTES (G_BYTES + H_BYTES)  // 36864
#define FULL_OFF (STAGES * STAGE_BYTES)  // 110592: full barriers (tx-based)
#define EMPTY_OFF (FULL_OFF + STAGES * 8)// 110616: empty barriers (8 arrivals)
#define SMEM_BYTES (EMPTY_OFF + STAGES * 8)  // 110640 -> 2 CTAs/SM (<=228KB)

static __device__ __forceinline__ uint32_t s2u(const void* p) {
    uint32_t a;
    asm("{ .reg .u64 t; cvta.to.shared.u64 t, %1; cvt.u32.u64 %0, t; }"
        : "=r"(a) : "l"(p));
    return a;
}

static __device__ __forceinline__ void mbar_init(uint32_t mbar, uint32_t cnt) {
    asm volatile("mbarrier.init.shared.b64 [%0], %1;" :: "r"(mbar), "r"(cnt) : "memory");
}

static __device__ __forceinline__ void mbar_expect_tx(uint32_t mbar, uint32_t bytes) {
    asm volatile("mbarrier.arrive.expect_tx.shared.b64 _, [%0], %1;"
                 :: "r"(mbar), "r"(bytes) : "memory");
}

static __device__ __forceinline__ void mbar_arrive(uint32_t mbar) {
    asm volatile("mbarrier.arrive.release.cta.shared::cta.b64 _, [%0];"
                 :: "r"(mbar) : "memory");
}

static __device__ __forceinline__ void mbar_wait(uint32_t mbar, uint32_t parity) {
    uint32_t done;
    asm volatile(
        "{\n\t.reg .pred p;\n\t"
        "mbarrier.try_wait.parity.acquire.cta.shared::cta.b64 p, [%1], %2;\n\t"
        "selp.b32 %0, 1, 0, p;\n\t}"
        : "=r"(done) : "r"(mbar), "r"(parity) : "memory");
    if (!done) {
        asm volatile(
            "{\n\t.reg .pred P1;\n\t"
            "WL_%=:\n\t"
            "mbarrier.try_wait.parity.acquire.cta.shared::cta.b64 P1, [%0], %1, 0x989680;\n\t"
            "@P1 bra.uni WD_%=;\n\t"
            "bra.uni WL_%=;\n\t"
            "WD_%=:\n\t}"
            :: "r"(mbar), "r"(parity) : "memory");
    }
}

static __device__ __forceinline__ void bulk_copy(uint32_t dst_smem, const void* src,
                                                 uint32_t bytes, uint32_t mbar) {
    asm volatile(
        "cp.async.bulk.shared::cta.global.mbarrier::complete_tx::bytes [%0], [%1], %2, [%3];"
        :: "r"(dst_smem), "l"(src), "r"(bytes), "r"(mbar) : "memory");
}

static __device__ __forceinline__ void fence_async_smem() {
    asm volatile("fence.proxy.async.shared::cta;" ::: "memory");
}

static __device__ __forceinline__ float ex2(float x) {
    float y;
    asm("ex2.approx.ftz.f32 %0, %1;" : "=f"(y) : "f"(x));
    return y;
}

// Fused ReservoirRNNCell step — single-wave resident TMA pipeline with a
// decoupled producer/consumer ring (NO per-iteration __syncthreads):
//   grid = 256 CTAs (one wave at 2 CTAs/SM). CTA = o-group (8 rows, W_hh
//   pre-scaled into 32 regs once) x 32 b-iterations over a 3-stage ring
//   (32KB gumbel + 4KB h_prev per stage).
//   Handshake per stage: full mbarrier (TMA tx-count) for fill completion;
//   empty mbarrier (arrive-count 8, one release-arrive per warp after its
//   reads) for consumption. Fast warps never wait for slow ones — they only
//   wait on full[st+1], issued 3 iterations earlier. Thread 0 alone waits
//   empty[st] (acquire), fence.proxy.async, then refills for tile i+3.
// Softmax without max-subtraction is safe: logits bounded (~18.5);
// validated rel_err 3.4e-7 in R1-R5/R7.
__global__ __launch_bounds__(256, 2) void reservoir_cell_kernel(
    const float* __restrict__ x_t,         // (B, I)
    const float* __restrict__ h_prev,      // (B, H)
    const float* __restrict__ W_ih,        // (H, I)
    const float* __restrict__ b_ih,        // (H,)
    const float* __restrict__ W_hh,        // (H, H)
    const float* __restrict__ temperature, // scalar
    const float* __restrict__ gumbel,      // (B, H, H)
    float* __restrict__ out)               // (B, H)
{
    extern __shared__ float smem[];
    const uint32_t smem_u = s2u(smem);
    const uint32_t fullb  = smem_u + FULL_OFF;
    const uint32_t emptyb = smem_u + EMPTY_OFF;

    const int og   = blockIdx.x & (OGROUPS - 1);   // 0..127
    const int half = blockIdx.x >> 7;              // 0..1
    const int b0 = half * BITERS;
    const int o0 = og * OW;

    const int tid  = threadIdx.x;
    const int w    = tid >> 5;
    const int lane = tid & 31;
    const int o    = o0 + w;

    // ---- init barriers + prologue fills (stages 0..2) ----
    if (tid == 0) {
#pragma unroll
        for (int j = 0; j < STAGES; ++j) {
            mbar_init(fullb + 8u * j, 1);
            mbar_init(emptyb + 8u * j, OW);   // one arrive per warp
        }
    }
    __syncthreads();
    if (tid == 0) {
#pragma unroll
        for (int j = 0; j < STAGES; ++j) {
            const uint32_t mb = fullb + 8u * j;
            mbar_expect_tx(mb, STAGE_BYTES);
            const float* gsrc = gumbel + ((size_t)(b0 + j) * HH + o0) * HH;
            bulk_copy(smem_u + j * STAGE_BYTES, gsrc, G_BYTES, mb);
            const float* hsrc = h_prev + (size_t)(b0 + j) * HH;
            bulk_copy(smem_u + j * STAGE_BYTES + G_BYTES, hsrc, H_BYTES, mb);
        }
    }

    // ---- per-warp constants, loaded ONCE per 32 tiles (overlaps TMA) ----
    const float inv_tau_l2e = LOG2E / fmaxf(temperature[0], MIN_TAU);
    const float bias = b_ih[o];

    const float4* __restrict__ whr = reinterpret_cast<const float4*>(W_hh + (size_t)o * HH);
    float4 wp[8];
#pragma unroll
    for (int k = 0; k < 8; ++k) {
        float4 v = whr[lane + 32 * k];
        v.x *= inv_tau_l2e; v.y *= inv_tau_l2e;
        v.z *= inv_tau_l2e; v.w *= inv_tau_l2e;
        wp[k] = v;
    }
    const float4* __restrict__ wir = reinterpret_cast<const float4*>(W_ih + (size_t)o * II);
    float4 wih[4];
#pragma unroll
    for (int k = 0; k < 4; ++k) wih[k] = wir[lane + 32 * k];

    // ---- steady-state loop over 32 b's through the 3-stage ring ----
    int st = 0;
    int parity = 0;   // stage-use parity: use k of stage st has parity k&1
    for (int i = 0; i < BITERS; ++i) {
        const int b = b0 + i;

        // input contribution (register-cached W_ih) — overlaps the wait
        const float4* __restrict__ xr = reinterpret_cast<const float4*>(x_t + (size_t)b * II);
        float ic = 0.0f;
#pragma unroll
        for (int k = 0; k < 4; ++k) {
            const float4 xv = xr[lane + 32 * k];
            ic = fmaf(xv.x, wih[k].x, ic);
            ic = fmaf(xv.y, wih[k].y, ic);
            ic = fmaf(xv.z, wih[k].z, ic);
            ic = fmaf(xv.w, wih[k].w, ic);
        }

        mbar_wait(fullb + 8u * st, parity);

        const float4* __restrict__ gs = reinterpret_cast<const float4*>(
            smem + (size_t)st * (STAGE_BYTES / 4) + (size_t)w * HH);
        const float4* __restrict__ hs = reinterpret_cast<const float4*>(
            smem + (size_t)st * (STAGE_BYTES / 4) + G_BYTES / 4);

        float s = 0.0f, t = 0.0f;
#pragma unroll
        for (int k = 0; k < 8; ++k) {
            const int idx = lane + 32 * k;
            const float4 g = gs[idx];
            const float4 h = hs[idx];
            float e;
            e = ex2(fmaf(g.x, LOG2E, wp[k].x)); s += e; t = fmaf(e, h.x, t);
            e = ex2(fmaf(g.y, LOG2E, wp[k].y)); s += e; t = fmaf(e, h.y, t);
            e = ex2(fmaf(g.z, LOG2E, wp[k].z)); s += e; t = fmaf(e, h.z, t);
            e = ex2(fmaf(g.w, LOG2E, wp[k].w)); s += e; t = fmaf(e, h.w, t);
        }

        // this warp is done with the stage (values live in registers):
        // release-arrive on the empty barrier and move on. No block sync.
        __syncwarp();
        if (lane == 0) mbar_arrive(emptyb + 8u * st);

        // producer duty (thread 0 only): wait all 8 warps done, then refill
        // stage st for tile i+3. Fast warps are NOT blocked by this.
        if (tid == 0 && i + STAGES < BITERS) {
            mbar_wait(emptyb + 8u * st, parity);  // acquire all warps' reads
            fence_async_smem();                   // order before async rewrite
            const int j = b0 + i + STAGES;
            const uint32_t mb = fullb + 8u * st;
            mbar_expect_tx(mb, STAGE_BYTES);
            const float* gsrc = gumbel + ((size_t)j * HH + o0) * HH;
            bulk_copy(smem_u + st * STAGE_BYTES, gsrc, G_BYTES, mb);
            const float* hsrc = h_prev + (size_t)j * HH;
            bulk_copy(smem_u + st * STAGE_BYTES + G_BYTES, hsrc, H_BYTES, mb);
        }

        // warp reductions + output (overlaps the refill)
#pragma unroll
        for (int off = 16; off > 0; off >>= 1) {
            s  += __shfl_xor_sync(0xffffffffu, s,  off);
            t  += __shfl_xor_sync(0xffffffffu, t,  off);
            ic += __shfl_xor_sync(0xffffffffu, ic, off);
        }
        if (lane == 0) {
            out[(size_t)b * HH + o] = tanhf(ic + bias + t / s);
        }

        if (++st == STAGES) { st = 0; parity ^= 1; }
    }
}

extern "C" void kernel_launch(void* const* d_in, const int* in_sizes, int n_in,
                              void* d_out, int out_size) {
    // metadata order: x_t, h_prev, W_ih, b_ih, W_hh, temperature, gumbel_noise
    const float* x_t    = (const float*)d_in[0];
    const float* h_prev = (const float*)d_in[1];
    const float* W_ih   = (const float*)d_in[2];
    const float* b_ih   = (const float*)d_in[3];
    const float* W_hh   = (const float*)d_in[4];
    const float* temp   = (const float*)d_in[5];
    const float* gum    = (const float*)d_in[6];
    float* out = (float*)d_out;

    static bool attr_set = false;
    if (!attr_set) {
        cudaFuncSetAttribute(reservoir_cell_kernel,
                             cudaFuncAttributeMaxDynamicSharedMemorySize, SMEM_BYTES);
        attr_set = true;
    }

    dim3 grid(OGROUPS * HALVES);   // 128 * 2 = 256 CTAs: one resident wave
    dim3 block(OW * 32);           // 256 threads, 8 warps
    reservoir_cell_kernel<<<grid, block, SMEM_BYTES>>>(
        x_t, h_prev, W_ih, b_ih, W_hh, temp, gum, out);
}

// round 9
// speedup vs baseline: 1.2433x; 1.0368x over previous
#include <cuda_runtime.h>
#include <cstdint>

// Problem constants
#define BB 64
#define HH 1024
#define II 512
#define MIN_TAU 1e-3f
#define LOG2E 1.4426950408889634f

// Tiling: 256 resident CTAs (single wave on 148 SMs x 2 CTAs).
// CTA = fixed o-group of 8 rows x 32 b-iterations.
// 8 consumer warps + 1 dedicated producer warp = 288 threads.
#define OW 8
#define NWARPS 9
#define BITERS 32
#define OGROUPS (HH / OW)       // 128
#define HALVES (BB / BITERS)    // 2
#define STAGES 3

// SMEM layout (dynamic)
#define G_BYTES (OW * HH * 4)            // 32768: gumbel[b, o0 .. o0+7, :]
#define H_BYTES (HH * 4)                 // 4096:  h_prev[b, :]
#define STAGE_BYTES (G_BYTES + H_BYTES)  // 36864
#define FULL_OFF (STAGES * STAGE_BYTES)  // full barriers (tx-based)
#define EMPTY_OFF (FULL_OFF + STAGES * 8)
#define SMEM_BYTES (EMPTY_OFF + STAGES * 8)  // 110640 -> 2 CTAs/SM (<=228KB)

static __device__ __forceinline__ uint32_t s2u(const void* p) {
    uint32_t a;
    asm("{ .reg .u64 t; cvta.to.shared.u64 t, %1; cvt.u32.u64 %0, t; }"
        : "=r"(a) : "l"(p));
    return a;
}

static __device__ __forceinline__ void mbar_init(uint32_t mbar, uint32_t cnt) {
    asm volatile("mbarrier.init.shared.b64 [%0], %1;" :: "r"(mbar), "r"(cnt) : "memory");
}

static __device__ __forceinline__ void mbar_expect_tx(uint32_t mbar, uint32_t bytes) {
    asm volatile("mbarrier.arrive.expect_tx.shared.b64 _, [%0], %1;"
                 :: "r"(mbar), "r"(bytes) : "memory");
}

static __device__ __forceinline__ void mbar_arrive(uint32_t mbar) {
    asm volatile("mbarrier.arrive.release.cta.shared::cta.b64 _, [%0];"
                 :: "r"(mbar) : "memory");
}

static __device__ __forceinline__ void mbar_wait(uint32_t mbar, uint32_t parity) {
    uint32_t done;
    asm volatile(
        "{\n\t.reg .pred p;\n\t"
        "mbarrier.try_wait.parity.acquire.cta.shared::cta.b64 p, [%1], %2;\n\t"
        "selp.b32 %0, 1, 0, p;\n\t}"
        : "=r"(done) : "r"(mbar), "r"(parity) : "memory");
    if (!done) {
        asm volatile(
            "{\n\t.reg .pred P1;\n\t"
            "WL_%=:\n\t"
            "mbarrier.try_wait.parity.acquire.cta.shared::cta.b64 P1, [%0], %1, 0x989680;\n\t"
            "@P1 bra.uni WD_%=;\n\t"
            "bra.uni WL_%=;\n\t"
            "WD_%=:\n\t}"
            :: "r"(mbar), "r"(parity) : "memory");
    }
}

static __device__ __forceinline__ void bulk_copy(uint32_t dst_smem, const void* src,
                                                 uint32_t bytes, uint32_t mbar) {
    asm volatile(
        "cp.async.bulk.shared::cta.global.mbarrier::complete_tx::bytes [%0], [%1], %2, [%3];"
        :: "r"(dst_smem), "l"(src), "r"(bytes), "r"(mbar) : "memory");
}

static __device__ __forceinline__ void fence_async_smem() {
    asm volatile("fence.proxy.async.shared::cta;" ::: "memory");
}

static __device__ __forceinline__ float ex2(float x) {
    float y;
    asm("ex2.approx.ftz.f32 %0, %1;" : "=f"(y) : "f"(x));
    return y;
}

// Fused ReservoirRNNCell step — single-wave resident TMA pipeline with a
// DEDICATED PRODUCER WARP (warp specialization):
//   grid = 256 CTAs (one wave at 2 CTAs/SM), 288 threads: warps 0-7 consume,
//   warp 8 produces. CTA = o-group (8 rows; W_hh pre-scaled into 32 regs
//   once) x 32 b-iterations over a 3-stage ring (32KB gumbel + 4KB h_prev
//   per stage).
//   Producer warp: for fill f (stage f%3, round r=f/3): wait empty[st]
//   parity (r-1)&1 (skip r=0), fence.proxy.async, expect_tx, 2 bulk copies.
//   Consumers: wait full[st] parity r&1, consume, release-arrive empty[st],
//   reduce, store. No consumer ever waits on another consumer — warp 0 is
//   no longer slowest-warp-coupled (R8's residual serialization).
// Softmax without max-subtraction is safe: logits bounded (~18.5);
// validated rel_err 3.4e-7 in R1-R5/R7/R8.
__global__ __launch_bounds__(288, 2) void reservoir_cell_kernel(
    const float* __restrict__ x_t,         // (B, I)
    const float* __restrict__ h_prev,      // (B, H)
    const float* __restrict__ W_ih,        // (H, I)
    const float* __restrict__ b_ih,        // (H,)
    const float* __restrict__ W_hh,        // (H, H)
    const float* __restrict__ temperature, // scalar
    const float* __restrict__ gumbel,      // (B, H, H)
    float* __restrict__ out)               // (B, H)
{
    extern __shared__ float smem[];
    const uint32_t smem_u = s2u(smem);
    const uint32_t fullb  = smem_u + FULL_OFF;
    const uint32_t emptyb = smem_u + EMPTY_OFF;

    const int og   = blockIdx.x & (OGROUPS - 1);   // 0..127
    const int half = blockIdx.x >> 7;              // 0..1
    const int b0 = half * BITERS;
    const int o0 = og * OW;

    const int tid  = threadIdx.x;
    const int w    = tid >> 5;
    const int lane = tid & 31;

    // ---- init barriers (all 9 warps participate in this one sync) ----
    if (tid == 0) {
#pragma unroll
        for (int j = 0; j < STAGES; ++j) {
            mbar_init(fullb + 8u * j, 1);
            mbar_init(emptyb + 8u * j, OW);   // one arrive per consumer warp
        }
    }
    __syncthreads();   // the ONLY block-wide sync

    // ================= PRODUCER WARP (w == 8) =================
    if (w == 8) {
        if (lane == 0) {
            int st = 0, r = 0;
            for (int f = 0; f < BITERS; ++f) {
                if (r >= 1) {
                    // all consumers done with round r-1 of this stage
                    mbar_wait(emptyb + 8u * st, (r - 1) & 1);
                    fence_async_smem();  // order their generic reads vs TMA write
                }
                const uint32_t mb = fullb + 8u * st;
                mbar_expect_tx(mb, STAGE_BYTES);
                const float* gsrc = gumbel + ((size_t)(b0 + f) * HH + o0) * HH;
                bulk_copy(smem_u + st * STAGE_BYTES, gsrc, G_BYTES, mb);
                const float* hsrc = h_prev + (size_t)(b0 + f) * HH;
                bulk_copy(smem_u + st * STAGE_BYTES + G_BYTES, hsrc, H_BYTES, mb);
                if (++st == STAGES) { st = 0; ++r; }
            }
        }
        return;
    }

    // ================= CONSUMER WARPS (w == 0..7) =================
    const int o = o0 + w;

    // per-warp constants, loaded ONCE per 32 tiles (overlaps prologue TMA)
    const float inv_tau_l2e = LOG2E / fmaxf(temperature[0], MIN_TAU);
    const float bias = b_ih[o];

    const float4* __restrict__ whr = reinterpret_cast<const float4*>(W_hh + (size_t)o * HH);
    float4 wp[8];
#pragma unroll
    for (int k = 0; k < 8; ++k) {
        float4 v = whr[lane + 32 * k];
        v.x *= inv_tau_l2e; v.y *= inv_tau_l2e;
        v.z *= inv_tau_l2e; v.w *= inv_tau_l2e;
        wp[k] = v;
    }
    const float4* __restrict__ wir = reinterpret_cast<const float4*>(W_ih + (size_t)o * II);
    float4 wih[4];
#pragma unroll
    for (int k = 0; k < 4; ++k) wih[k] = wir[lane + 32 * k];

    int st = 0;
    int parity = 0;   // round parity: r = i/STAGES, parity = r&1
    for (int i = 0; i < BITERS; ++i) {
        const int b = b0 + i;

        // input contribution (register-cached W_ih) — overlaps the wait
        const float4* __restrict__ xr = reinterpret_cast<const float4*>(x_t + (size_t)b * II);
        float ic = 0.0f;
#pragma unroll
        for (int k = 0; k < 4; ++k) {
            const float4 xv = xr[lane + 32 * k];
            ic = fmaf(xv.x, wih[k].x, ic);
            ic = fmaf(xv.y, wih[k].y, ic);
            ic = fmaf(xv.z, wih[k].z, ic);
            ic = fmaf(xv.w, wih[k].w, ic);
        }

        mbar_wait(fullb + 8u * st, parity);

        const float4* __restrict__ gs = reinterpret_cast<const float4*>(
            smem + (size_t)st * (STAGE_BYTES / 4) + (size_t)w * HH);
        const float4* __restrict__ hs = reinterpret_cast<const float4*>(
            smem + (size_t)st * (STAGE_BYTES / 4) + G_BYTES / 4);

        float s = 0.0f, t = 0.0f;
#pragma unroll
        for (int k = 0; k < 8; ++k) {
            const int idx = lane + 32 * k;
            const float4 g = gs[idx];
            const float4 h = hs[idx];
            float e;
            e = ex2(fmaf(g.x, LOG2E, wp[k].x)); s += e; t = fmaf(e, h.x, t);
            e = ex2(fmaf(g.y, LOG2E, wp[k].y)); s += e; t = fmaf(e, h.y, t);
            e = ex2(fmaf(g.z, LOG2E, wp[k].z)); s += e; t = fmaf(e, h.z, t);
            e = ex2(fmaf(g.w, LOG2E, wp[k].w)); s += e; t = fmaf(e, h.w, t);
        }

        // stage data consumed into registers: signal the producer and go on.
        __syncwarp();
        if (lane == 0) mbar_arrive(emptyb + 8u * st);

        // warp reductions + output (overlaps the producer's refill)
#pragma unroll
        for (int off = 16; off > 0; off >>= 1) {
            s  += __shfl_xor_sync(0xffffffffu, s,  off);
            t  += __shfl_xor_sync(0xffffffffu, t,  off);
            ic += __shfl_xor_sync(0xffffffffu, ic, off);
        }
        if (lane == 0) {
            out[(size_t)b * HH + o] = tanhf(ic + bias + t / s);
        }

        if (++st == STAGES) { st = 0; parity ^= 1; }
    }
}

extern "C" void kernel_launch(void* const* d_in, const int* in_sizes, int n_in,
                              void* d_out, int out_size) {
    // metadata order: x_t, h_prev, W_ih, b_ih, W_hh, temperature, gumbel_noise
    const float* x_t    = (const float*)d_in[0];
    const float* h_prev = (const float*)d_in[1];
    const float* W_ih   = (const float*)d_in[2];
    const float* b_ih   = (const float*)d_in[3];
    const float* W_hh   = (const float*)d_in[4];
    const float* temp   = (const float*)d_in[5];
    const float* gum    = (const float*)d_in[6];
    float* out = (float*)d_out;

    static bool attr_set = false;
    if (!attr_set) {
        cudaFuncSetAttribute(reservoir_cell_kernel,
                             cudaFuncAttributeMaxDynamicSharedMemorySize, SMEM_BYTES);
        attr_set = true;
    }

    dim3 grid(OGROUPS * HALVES);   // 128 * 2 = 256 CTAs: one resident wave
    dim3 block(NWARPS * 32);       // 288 threads: 8 consumer + 1 producer warp
    reservoir_cell_kernel<<<grid, block, SMEM_BYTES>>>(
        x_t, h_prev, W_ih, b_ih, W_hh, temp, gum, out);
}